// round 7
// baseline (speedup 1.0000x reference)
#include <cuda_runtime.h>
#include <math.h>

#define LSEQ   1024
#define DMODEL 1024
#define NHEADS 16
#define DHEAD  64
#define NBATCH 8
#define NROWS  (NBATCH * LSEQ)   // 8192

static __device__ float g_Q[NROWS * DMODEL];
static __device__ float g_K[NROWS * DMODEL];
static __device__ float g_V[NROWS * DMODEL];
static __device__ float g_CTX[NROWS * DMODEL];
static __device__ float g_Y[NROWS * DMODEL];
static __device__ float g_S[(size_t)NBATCH * NHEADS * LSEQ * LSEQ];

// ---------------------------------------------------------------------------
__device__ __forceinline__ void tf32_split_u(float x, unsigned& hi, unsigned& lo) {
    asm("cvt.rna.tf32.f32 %0, %1;" : "=r"(hi) : "f"(x));
    float r = x - __uint_as_float(hi);
    asm("cvt.rna.tf32.f32 %0, %1;" : "=r"(lo) : "f"(r));
}

__device__ __forceinline__ void mma8(float* c, const unsigned* a, const unsigned* b) {
    asm volatile(
        "mma.sync.aligned.m16n8k8.row.col.f32.tf32.tf32.f32 "
        "{%0,%1,%2,%3}, {%4,%5,%6,%7}, {%8,%9}, {%0,%1,%2,%3};"
        : "+f"(c[0]), "+f"(c[1]), "+f"(c[2]), "+f"(c[3])
        : "r"(a[0]), "r"(a[1]), "r"(a[2]), "r"(a[3]), "r"(b[0]), "r"(b[1]));
}

#define PAD_A 136   // row stride: 136 mod 32 = 8 -> 4 rows x 8 cols hit 32 distinct banks
#define PAD_B 72

// load one 16-row m-group of RAW A values and split to hi/lo fragments
__device__ __forceinline__ void frag_a_raw(const float (*As)[PAD_A], int ks, int tig,
                                           int m, unsigned* aH, unsigned* aL) {
    tf32_split_u(As[ks + tig    ][m    ], aH[0], aL[0]);
    tf32_split_u(As[ks + tig    ][m + 8], aH[1], aL[1]);
    tf32_split_u(As[ks + tig + 4][m    ], aH[2], aL[2]);
    tf32_split_u(As[ks + tig + 4][m + 8], aH[3], aL[3]);
}

// ---------------------------------------------------------------------------
// Dense NN GEMM: C[M,1024] = A[M,K] @ B[K,1024] (+R). 3xTF32, raw-smem.
// BM=BN=128, BK=16, 8 warps, warp tile 64x32. grid=(8, M/128).
// ---------------------------------------------------------------------------
__global__ __launch_bounds__(256, 2) void mma_nn_kernel(
    const float* __restrict__ A, const float* __restrict__ B,
    float* __restrict__ C, const float* __restrict__ R, int K)
{
    const int N = DMODEL;
    __shared__ float As[16][PAD_A];   // transposed A tile, raw fp32
    __shared__ float Bs[16][PAD_A];   // B tile, raw fp32

    const int tid = threadIdx.x;
    const int wid = tid >> 5, lane = tid & 31;
    const int gid = lane >> 2, tig = lane & 3;
    const int wm = (wid & 1) * 64, wn = (wid >> 1) * 32;
    const int bm = blockIdx.y * 128, bn = blockIdx.x * 128;

    float acc[4][4][4] = {};

    for (int k0 = 0; k0 < K; k0 += 16) {
        #pragma unroll
        for (int t = 0; t < 2; t++) {
            int id = tid + t * 256;
            int r = id >> 2, c = (id & 3) << 2;
            float4 v = *(const float4*)(A + (size_t)(bm + r) * K + k0 + c);
            As[c][r] = v.x; As[c + 1][r] = v.y; As[c + 2][r] = v.z; As[c + 3][r] = v.w;
        }
        #pragma unroll
        for (int t = 0; t < 2; t++) {
            int id = tid + t * 256;
            int r = id >> 5, c = (id & 31) << 2;
            *(float4*)(&Bs[r][c]) = *(const float4*)(B + (size_t)(k0 + r) * N + bn + c);
        }
        __syncthreads();

        #pragma unroll
        for (int ks = 0; ks < 16; ks += 8) {
            unsigned aH[4][4], aL[4][4];
            #pragma unroll
            for (int mf = 0; mf < 4; mf++)
                frag_a_raw(As, ks, tig, wm + mf * 16 + gid, aH[mf], aL[mf]);
            #pragma unroll
            for (int nf = 0; nf < 4; nf++) {
                int n = wn + nf * 8 + gid;
                unsigned bH[2], bL[2];
                tf32_split_u(Bs[ks + tig    ][n], bH[0], bL[0]);
                tf32_split_u(Bs[ks + tig + 4][n], bH[1], bL[1]);
                #pragma unroll
                for (int mf = 0; mf < 4; mf++) {
                    mma8(acc[mf][nf], aH[mf], bH);
                    mma8(acc[mf][nf], aH[mf], bL);
                    mma8(acc[mf][nf], aL[mf], bH);
                }
            }
        }
        __syncthreads();
    }

    #pragma unroll
    for (int mf = 0; mf < 4; mf++) {
        #pragma unroll
        for (int nf = 0; nf < 4; nf++) {
            int m = bm + wm + mf * 16 + gid;
            int n = bn + wn + nf * 8 + 2 * tig;
            float2 v0 = make_float2(acc[mf][nf][0], acc[mf][nf][1]);
            float2 v1 = make_float2(acc[mf][nf][2], acc[mf][nf][3]);
            if (R) {
                float2 r0 = *(const float2*)(R + (size_t)m * N + n);
                float2 r1 = *(const float2*)(R + (size_t)(m + 8) * N + n);
                v0.x += r0.x; v0.y += r0.y; v1.x += r1.x; v1.y += r1.y;
            }
            *(float2*)(C + (size_t)m * N + n) = v0;
            *(float2*)(C + (size_t)(m + 8) * N + n) = v1;
        }
    }
}

// ---------------------------------------------------------------------------
// Scores: per (b,h): S = 0.125 * Q @ K^T, masked. 3xTF32, raw-smem.
// grid = (8, 8, 128).
// ---------------------------------------------------------------------------
__global__ __launch_bounds__(256, 2) void mma_scores_kernel(
    const float* __restrict__ Qg, const float* __restrict__ Kg,
    float* __restrict__ S, const unsigned int* __restrict__ mask)
{
    const int z = blockIdx.z, b = z >> 4, h = z & 15;
    const float* Aq = Qg + (size_t)b * LSEQ * DMODEL + h * DHEAD;
    const float* Bk = Kg + (size_t)b * LSEQ * DMODEL + h * DHEAD;
    float* C = S + (size_t)z * LSEQ * LSEQ;
    const unsigned int* mb = mask + (size_t)b * LSEQ * LSEQ;

    __shared__ float As[16][PAD_A];
    __shared__ float Bs[16][PAD_A];

    const int tid = threadIdx.x;
    const int wid = tid >> 5, lane = tid & 31;
    const int gid = lane >> 2, tig = lane & 3;
    const int wm = (wid & 1) * 64, wn = (wid >> 1) * 32;
    const int bm = blockIdx.y * 128, bn = blockIdx.x * 128;

    float acc[4][4][4] = {};

    for (int k0 = 0; k0 < DHEAD; k0 += 16) {
        #pragma unroll
        for (int t = 0; t < 2; t++) {
            int id = tid + t * 256;
            int r = id >> 2, c = (id & 3) << 2;
            float4 v = *(const float4*)(Aq + (size_t)(bm + r) * DMODEL + k0 + c);
            As[c][r] = v.x; As[c + 1][r] = v.y; As[c + 2][r] = v.z; As[c + 3][r] = v.w;
            float4 w = *(const float4*)(Bk + (size_t)(bn + r) * DMODEL + k0 + c);
            Bs[c][r] = w.x; Bs[c + 1][r] = w.y; Bs[c + 2][r] = w.z; Bs[c + 3][r] = w.w;
        }
        __syncthreads();

        #pragma unroll
        for (int ks = 0; ks < 16; ks += 8) {
            unsigned aH[4][4], aL[4][4];
            #pragma unroll
            for (int mf = 0; mf < 4; mf++)
                frag_a_raw(As, ks, tig, wm + mf * 16 + gid, aH[mf], aL[mf]);
            #pragma unroll
            for (int nf = 0; nf < 4; nf++) {
                int n = wn + nf * 8 + gid;
                unsigned bH[2], bL[2];
                tf32_split_u(Bs[ks + tig    ][n], bH[0], bL[0]);
                tf32_split_u(Bs[ks + tig + 4][n], bH[1], bL[1]);
                #pragma unroll
                for (int mf = 0; mf < 4; mf++) {
                    mma8(acc[mf][nf], aH[mf], bH);
                    mma8(acc[mf][nf], aH[mf], bL);
                    mma8(acc[mf][nf], aL[mf], bH);
                }
            }
        }
        __syncthreads();
    }

    const float scale = 0.125f;
    #pragma unroll
    for (int mf = 0; mf < 4; mf++) {
        #pragma unroll
        for (int nf = 0; nf < 4; nf++) {
            int m = bm + wm + mf * 16 + gid;
            int n = bn + wn + nf * 8 + 2 * tig;
            #pragma unroll
            for (int half = 0; half < 2; half++) {
                int q = m + half * 8;
                float s0 = acc[mf][nf][half * 2]     * scale;
                float s1 = acc[mf][nf][half * 2 + 1] * scale;
                if (mb[(size_t)q * LSEQ + n]     != 0u) s0 = -1e9f;
                if (mb[(size_t)q * LSEQ + n + 1] != 0u) s1 = -1e9f;
                *(float2*)(C + (size_t)q * LSEQ + n) = make_float2(s0, s1);
            }
        }
    }
}

// ---------------------------------------------------------------------------
__global__ __launch_bounds__(256) void softmax_kernel(float* __restrict__ S)
{
    __shared__ float red[256];
    float* p = S + (size_t)blockIdx.x * LSEQ;
    const int tid = threadIdx.x;
    float4 v = *(float4*)(p + tid * 4);
    red[tid] = fmaxf(fmaxf(v.x, v.y), fmaxf(v.z, v.w));
    __syncthreads();
    for (int s = 128; s > 0; s >>= 1) {
        if (tid < s) red[tid] = fmaxf(red[tid], red[tid + s]);
        __syncthreads();
    }
    const float mx = red[0];
    __syncthreads();
    v.x = __expf(v.x - mx); v.y = __expf(v.y - mx);
    v.z = __expf(v.z - mx); v.w = __expf(v.w - mx);
    red[tid] = v.x + v.y + v.z + v.w;
    __syncthreads();
    for (int s = 128; s > 0; s >>= 1) {
        if (tid < s) red[tid] += red[tid + s];
        __syncthreads();
    }
    const float inv = 1.0f / red[0];
    v.x *= inv; v.y *= inv; v.z *= inv; v.w *= inv;
    *(float4*)(p + tid * 4) = v;
}

// ---------------------------------------------------------------------------
// Context: per (b,h): CTX = attn @ V[1024,64]. 3xTF32, raw-smem.
// BM=128, BN=64. grid = (1, 8, 128).
// ---------------------------------------------------------------------------
__global__ __launch_bounds__(256, 2) void mma_av_kernel(
    const float* __restrict__ S, const float* __restrict__ Vg, float* __restrict__ CTX)
{
    const int z = blockIdx.z, b = z >> 4, h = z & 15;
    const float* A  = S + (size_t)z * LSEQ * LSEQ;
    const float* Bp = Vg + (size_t)b * LSEQ * DMODEL + h * DHEAD;
    float* C = CTX + (size_t)b * LSEQ * DMODEL + h * DHEAD;

    __shared__ float As[16][PAD_A];
    __shared__ float Bs[16][PAD_B];

    const int tid = threadIdx.x;
    const int wid = tid >> 5, lane = tid & 31;
    const int gid = lane >> 2, tig = lane & 3;
    const int wm = (wid & 1) * 64, wn = (wid >> 1) * 16;
    const int bm = blockIdx.y * 128;

    float acc[4][2][4] = {};

    for (int k0 = 0; k0 < LSEQ; k0 += 16) {
        #pragma unroll
        for (int t = 0; t < 2; t++) {
            int id = tid + t * 256;
            int r = id >> 2, c = (id & 3) << 2;
            float4 v = *(const float4*)(A + (size_t)(bm + r) * LSEQ + k0 + c);
            As[c][r] = v.x; As[c + 1][r] = v.y; As[c + 2][r] = v.z; As[c + 3][r] = v.w;
        }
        {
            int r = tid >> 4, c = (tid & 15) << 2;
            *(float4*)(&Bs[r][c]) = *(const float4*)(Bp + (size_t)(k0 + r) * DMODEL + c);
        }
        __syncthreads();

        #pragma unroll
        for (int ks = 0; ks < 16; ks += 8) {
            unsigned aH[4][4], aL[4][4];
            #pragma unroll
            for (int mf = 0; mf < 4; mf++)
                frag_a_raw(As, ks, tig, wm + mf * 16 + gid, aH[mf], aL[mf]);
            #pragma unroll
            for (int nf = 0; nf < 2; nf++) {
                int n = wn + nf * 8 + gid;
                unsigned bH[2], bL[2];
                tf32_split_u(Bs[ks + tig    ][n], bH[0], bL[0]);
                tf32_split_u(Bs[ks + tig + 4][n], bH[1], bL[1]);
                #pragma unroll
                for (int mf = 0; mf < 4; mf++) {
                    mma8(acc[mf][nf], aH[mf], bH);
                    mma8(acc[mf][nf], aH[mf], bL);
                    mma8(acc[mf][nf], aL[mf], bH);
                }
            }
        }
        __syncthreads();
    }

    #pragma unroll
    for (int mf = 0; mf < 4; mf++) {
        #pragma unroll
        for (int nf = 0; nf < 2; nf++) {
            int m = bm + wm + mf * 16 + gid;
            int n = wn + nf * 8 + 2 * tig;
            *(float2*)(C + (size_t)m * DMODEL + n) =
                make_float2(acc[mf][nf][0], acc[mf][nf][1]);
            *(float2*)(C + (size_t)(m + 8) * DMODEL + n) =
                make_float2(acc[mf][nf][2], acc[mf][nf][3]);
        }
    }
}

// ---------------------------------------------------------------------------
__global__ __launch_bounds__(256) void ln_kernel(
    const float* __restrict__ Y, float* __restrict__ O,
    const float* __restrict__ gamma, const float* __restrict__ beta)
{
    __shared__ float red[256];
    const float* p = Y + (size_t)blockIdx.x * DMODEL;
    const int tid = threadIdx.x;
    float4 v = *(const float4*)(p + tid * 4);
    red[tid] = v.x + v.y + v.z + v.w;
    __syncthreads();
    for (int s = 128; s > 0; s >>= 1) {
        if (tid < s) red[tid] += red[tid + s];
        __syncthreads();
    }
    const float mu = red[0] * (1.0f / DMODEL);
    __syncthreads();
    const float dx = v.x - mu, dy = v.y - mu, dz = v.z - mu, dw = v.w - mu;
    red[tid] = dx * dx + dy * dy + dz * dz + dw * dw;
    __syncthreads();
    for (int s = 128; s > 0; s >>= 1) {
        if (tid < s) red[tid] += red[tid + s];
        __syncthreads();
    }
    const float rstd = rsqrtf(red[0] * (1.0f / DMODEL) + 1e-6f);
    const float4 g  = *(const float4*)(gamma + tid * 4);
    const float4 be = *(const float4*)(beta + tid * 4);
    float4 o;
    o.x = dx * rstd * g.x + be.x;
    o.y = dy * rstd * g.y + be.y;
    o.z = dz * rstd * g.z + be.z;
    o.w = dw * rstd * g.w + be.w;
    *(float4*)(O + (size_t)blockIdx.x * DMODEL + tid * 4) = o;
}

// ---------------------------------------------------------------------------
extern "C" void kernel_launch(void* const* d_in, const int* in_sizes, int n_in,
                              void* d_out, int out_size)
{
    const float* X    = (const float*)d_in[0];
    const unsigned int* mask = (const unsigned int*)d_in[1];
    const float* W_Q  = (const float*)d_in[2];
    const float* W_K  = (const float*)d_in[3];
    const float* W_V  = (const float*)d_in[4];
    const float* W_O  = (const float*)d_in[5];
    const float* gamma = (const float*)d_in[6];
    const float* beta  = (const float*)d_in[7];

    float *Qp, *Kp, *Vp, *Cp, *Yp, *Sp;
    cudaGetSymbolAddress((void**)&Qp, g_Q);
    cudaGetSymbolAddress((void**)&Kp, g_K);
    cudaGetSymbolAddress((void**)&Vp, g_V);
    cudaGetSymbolAddress((void**)&Cp, g_CTX);
    cudaGetSymbolAddress((void**)&Yp, g_Y);
    cudaGetSymbolAddress((void**)&Sp, g_S);

    const size_t LN_ELEMS   = (size_t)NROWS * DMODEL;
    const size_t ATTN_ELEMS = (size_t)NBATCH * NHEADS * LSEQ * LSEQ;

    float* out_ln;
    float* attn_dst;
    if ((size_t)out_size >= LN_ELEMS + ATTN_ELEMS) {
        out_ln = (float*)d_out;
        attn_dst = (float*)d_out + LN_ELEMS;
    } else if ((size_t)out_size == ATTN_ELEMS) {
        attn_dst = (float*)d_out;
        out_ln = Yp;
    } else {
        out_ln = (float*)d_out;
        attn_dst = Sp;
    }

    dim3 thr(256);
    mma_nn_kernel<<<dim3(8, 64), thr>>>(X, W_Q, Qp, nullptr, DMODEL);
    mma_nn_kernel<<<dim3(8, 64), thr>>>(X, W_K, Kp, nullptr, DMODEL);
    mma_nn_kernel<<<dim3(8, 64), thr>>>(X, W_V, Vp, nullptr, DMODEL);
    mma_scores_kernel<<<dim3(8, 8, NBATCH * NHEADS), thr>>>(Qp, Kp, attn_dst, mask);
    softmax_kernel<<<dim3(NBATCH * NHEADS * LSEQ), thr>>>(attn_dst);
    mma_av_kernel<<<dim3(1, 8, NBATCH * NHEADS), thr>>>(attn_dst, Vp, Cp);
    mma_nn_kernel<<<dim3(8, 64), thr>>>(Cp, W_O, Yp, X, DMODEL);
    ln_kernel<<<dim3(NROWS), thr>>>(Yp, out_ln, gamma, beta);
}

// round 8
// speedup vs baseline: 2.1755x; 2.1755x over previous
#include <cuda_runtime.h>
#include <cuda_bf16.h>
#include <math.h>

#define LSEQ   1024
#define DMODEL 1024
#define NHEADS 16
#define DHEAD  64
#define NBATCH 8
#define NROWS  (NBATCH * LSEQ)   // 8192

static __device__ float g_Q[NROWS * DMODEL];
static __device__ float g_K[NROWS * DMODEL];
static __device__ float g_V[NROWS * DMODEL];
static __device__ float g_CTX[NROWS * DMODEL];
static __device__ float g_Y[NROWS * DMODEL];
static __device__ float g_S[(size_t)NBATCH * NHEADS * LSEQ * LSEQ];

// ---------------------------------------------------------------------------
// Split two fp32 values (consecutive along k: x0 = even k, x1 = odd k) into
// packed bf16x2 hi and lo (residual) words.  lo half of word = x0.
// ---------------------------------------------------------------------------
__device__ __forceinline__ void bf16_split2(float x0, float x1,
                                            unsigned& hi_w, unsigned& lo_w) {
    asm("cvt.rn.bf16x2.f32 %0, %1, %2;" : "=r"(hi_w) : "f"(x1), "f"(x0));
    __nv_bfloat162 hv = *reinterpret_cast<__nv_bfloat162*>(&hi_w);
    float r0 = x0 - __bfloat162float(hv.x);
    float r1 = x1 - __bfloat162float(hv.y);
    asm("cvt.rn.bf16x2.f32 %0, %1, %2;" : "=r"(lo_w) : "f"(r1), "f"(r0));
}

// m16n8k16 bf16 MMA, fp32 accumulate
__device__ __forceinline__ void mma16(float* c, const unsigned* a, const unsigned* b) {
    asm volatile(
        "mma.sync.aligned.m16n8k16.row.col.f32.bf16.bf16.f32 "
        "{%0,%1,%2,%3}, {%4,%5,%6,%7}, {%8,%9}, {%0,%1,%2,%3};"
        : "+f"(c[0]), "+f"(c[1]), "+f"(c[2]), "+f"(c[3])
        : "r"(a[0]), "r"(a[1]), "r"(a[2]), "r"(a[3]), "r"(b[0]), "r"(b[1]));
}

#define PAD_A 136   // word stride: 136 mod 32 = 8 -> frag loads (8*tig+gid) conflict-free
#define PAD_B 72

// A-fragment load from packed transposed tile [k2][m]
__device__ __forceinline__ void frag_a(const unsigned (*T)[PAD_A], int tig, int m,
                                       unsigned* a) {
    a[0] = T[tig    ][m    ];
    a[1] = T[tig    ][m + 8];
    a[2] = T[tig + 4][m    ];
    a[3] = T[tig + 4][m + 8];
}

// ---------------------------------------------------------------------------
// Dense NN GEMM: C[M,1024] = A[M,K] @ B[K,1024] (+R). bf16-3x, k16 MMA.
// BM=BN=128, BK=16, 8 warps, warp tile 64x32. grid=(8, M/128).
// ---------------------------------------------------------------------------
__global__ __launch_bounds__(256) void mma_nn_kernel(
    const float* __restrict__ A, const float* __restrict__ B,
    float* __restrict__ C, const float* __restrict__ R, int K)
{
    const int N = DMODEL;
    __shared__ unsigned AsH[8][PAD_A], AsL[8][PAD_A];   // transposed A, packed k-pairs
    __shared__ unsigned BsH[8][PAD_A], BsL[8][PAD_A];   // B, packed k-pairs

    const int tid = threadIdx.x;
    const int wid = tid >> 5, lane = tid & 31;
    const int gid = lane >> 2, tig = lane & 3;
    const int wm = (wid & 1) * 64, wn = (wid >> 1) * 32;
    const int bm = blockIdx.y * 128, bn = blockIdx.x * 128;

    float acc[4][4][4] = {};

    for (int k0 = 0; k0 < K; k0 += 16) {
        // A tile 128x16 -> transposed packed [k2][m]
        #pragma unroll
        for (int t = 0; t < 2; t++) {
            int id = tid + t * 256;
            int r = id >> 2, c = (id & 3) << 2, k2 = c >> 1;
            float4 v = *(const float4*)(A + (size_t)(bm + r) * K + k0 + c);
            unsigned h0, l0, h1, l1;
            bf16_split2(v.x, v.y, h0, l0);
            bf16_split2(v.z, v.w, h1, l1);
            AsH[k2][r] = h0; AsL[k2][r] = l0;
            AsH[k2 + 1][r] = h1; AsL[k2 + 1][r] = l1;
        }
        // B tile 16x128 -> packed [k2][n]; pair two consecutive k rows
        {
            int k2 = tid >> 5, n = (tid & 31) << 2;
            const float* p = B + (size_t)(k0 + 2 * k2) * N + bn + n;
            float4 r0 = *(const float4*)p;
            float4 r1 = *(const float4*)(p + N);
            unsigned h, l;
            bf16_split2(r0.x, r1.x, h, l); BsH[k2][n]     = h; BsL[k2][n]     = l;
            bf16_split2(r0.y, r1.y, h, l); BsH[k2][n + 1] = h; BsL[k2][n + 1] = l;
            bf16_split2(r0.z, r1.z, h, l); BsH[k2][n + 2] = h; BsL[k2][n + 2] = l;
            bf16_split2(r0.w, r1.w, h, l); BsH[k2][n + 3] = h; BsL[k2][n + 3] = l;
        }
        __syncthreads();

        unsigned aH[4][4], aL[4][4];
        #pragma unroll
        for (int mf = 0; mf < 4; mf++) {
            frag_a(AsH, tig, wm + mf * 16 + gid, aH[mf]);
            frag_a(AsL, tig, wm + mf * 16 + gid, aL[mf]);
        }
        #pragma unroll
        for (int nf = 0; nf < 4; nf++) {
            int n = wn + nf * 8 + gid;
            unsigned bH[2] = { BsH[tig][n], BsH[tig + 4][n] };
            unsigned bL[2] = { BsL[tig][n], BsL[tig + 4][n] };
            #pragma unroll
            for (int mf = 0; mf < 4; mf++) {
                mma16(acc[mf][nf], aH[mf], bH);
                mma16(acc[mf][nf], aH[mf], bL);
                mma16(acc[mf][nf], aL[mf], bH);
            }
        }
        __syncthreads();
    }

    #pragma unroll
    for (int mf = 0; mf < 4; mf++) {
        #pragma unroll
        for (int nf = 0; nf < 4; nf++) {
            int m = bm + wm + mf * 16 + gid;
            int n = bn + wn + nf * 8 + 2 * tig;
            float2 v0 = make_float2(acc[mf][nf][0], acc[mf][nf][1]);
            float2 v1 = make_float2(acc[mf][nf][2], acc[mf][nf][3]);
            if (R) {
                float2 r0 = *(const float2*)(R + (size_t)m * N + n);
                float2 r1 = *(const float2*)(R + (size_t)(m + 8) * N + n);
                v0.x += r0.x; v0.y += r0.y; v1.x += r1.x; v1.y += r1.y;
            }
            *(float2*)(C + (size_t)m * N + n) = v0;
            *(float2*)(C + (size_t)(m + 8) * N + n) = v1;
        }
    }
}

// ---------------------------------------------------------------------------
// Scores: per (b,h): S = 0.125 * Q @ K^T, masked. bf16-3x, k16 MMA.
// grid = (8, 8, 128).
// ---------------------------------------------------------------------------
__global__ __launch_bounds__(256) void mma_scores_kernel(
    const float* __restrict__ Qg, const float* __restrict__ Kg,
    float* __restrict__ S, const unsigned int* __restrict__ mask)
{
    const int z = blockIdx.z, b = z >> 4, h = z & 15;
    const float* Aq = Qg + (size_t)b * LSEQ * DMODEL + h * DHEAD;
    const float* Bk = Kg + (size_t)b * LSEQ * DMODEL + h * DHEAD;
    float* C = S + (size_t)z * LSEQ * LSEQ;
    const unsigned int* mb = mask + (size_t)b * LSEQ * LSEQ;

    __shared__ unsigned AsH[8][PAD_A], AsL[8][PAD_A];
    __shared__ unsigned BsH[8][PAD_A], BsL[8][PAD_A];

    const int tid = threadIdx.x;
    const int wid = tid >> 5, lane = tid & 31;
    const int gid = lane >> 2, tig = lane & 3;
    const int wm = (wid & 1) * 64, wn = (wid >> 1) * 32;
    const int bm = blockIdx.y * 128, bn = blockIdx.x * 128;

    float acc[4][4][4] = {};

    for (int k0 = 0; k0 < DHEAD; k0 += 16) {
        #pragma unroll
        for (int t = 0; t < 2; t++) {
            int id = tid + t * 256;
            int r = id >> 2, c = (id & 3) << 2, k2 = c >> 1;
            float4 v = *(const float4*)(Aq + (size_t)(bm + r) * DMODEL + k0 + c);
            unsigned h0, l0, h1, l1;
            bf16_split2(v.x, v.y, h0, l0);
            bf16_split2(v.z, v.w, h1, l1);
            AsH[k2][r] = h0; AsL[k2][r] = l0;
            AsH[k2 + 1][r] = h1; AsL[k2 + 1][r] = l1;
            float4 w = *(const float4*)(Bk + (size_t)(bn + r) * DMODEL + k0 + c);
            bf16_split2(w.x, w.y, h0, l0);
            bf16_split2(w.z, w.w, h1, l1);
            BsH[k2][r] = h0; BsL[k2][r] = l0;
            BsH[k2 + 1][r] = h1; BsL[k2 + 1][r] = l1;
        }
        __syncthreads();

        unsigned aH[4][4], aL[4][4];
        #pragma unroll
        for (int mf = 0; mf < 4; mf++) {
            frag_a(AsH, tig, wm + mf * 16 + gid, aH[mf]);
            frag_a(AsL, tig, wm + mf * 16 + gid, aL[mf]);
        }
        #pragma unroll
        for (int nf = 0; nf < 4; nf++) {
            int n = wn + nf * 8 + gid;
            unsigned bH[2] = { BsH[tig][n], BsH[tig + 4][n] };
            unsigned bL[2] = { BsL[tig][n], BsL[tig + 4][n] };
            #pragma unroll
            for (int mf = 0; mf < 4; mf++) {
                mma16(acc[mf][nf], aH[mf], bH);
                mma16(acc[mf][nf], aH[mf], bL);
                mma16(acc[mf][nf], aL[mf], bH);
            }
        }
        __syncthreads();
    }

    const float scale = 0.125f;
    #pragma unroll
    for (int mf = 0; mf < 4; mf++) {
        #pragma unroll
        for (int nf = 0; nf < 4; nf++) {
            int m = bm + wm + mf * 16 + gid;
            int n = bn + wn + nf * 8 + 2 * tig;
            #pragma unroll
            for (int half = 0; half < 2; half++) {
                int q = m + half * 8;
                float s0 = acc[mf][nf][half * 2]     * scale;
                float s1 = acc[mf][nf][half * 2 + 1] * scale;
                if (mb[(size_t)q * LSEQ + n]     != 0u) s0 = -1e9f;
                if (mb[(size_t)q * LSEQ + n + 1] != 0u) s1 = -1e9f;
                *(float2*)(C + (size_t)q * LSEQ + n) = make_float2(s0, s1);
            }
        }
    }
}

// ---------------------------------------------------------------------------
__global__ __launch_bounds__(256) void softmax_kernel(float* __restrict__ S)
{
    __shared__ float red[256];
    float* p = S + (size_t)blockIdx.x * LSEQ;
    const int tid = threadIdx.x;
    float4 v = *(float4*)(p + tid * 4);
    red[tid] = fmaxf(fmaxf(v.x, v.y), fmaxf(v.z, v.w));
    __syncthreads();
    for (int s = 128; s > 0; s >>= 1) {
        if (tid < s) red[tid] = fmaxf(red[tid], red[tid + s]);
        __syncthreads();
    }
    const float mx = red[0];
    __syncthreads();
    v.x = __expf(v.x - mx); v.y = __expf(v.y - mx);
    v.z = __expf(v.z - mx); v.w = __expf(v.w - mx);
    red[tid] = v.x + v.y + v.z + v.w;
    __syncthreads();
    for (int s = 128; s > 0; s >>= 1) {
        if (tid < s) red[tid] += red[tid + s];
        __syncthreads();
    }
    const float inv = 1.0f / red[0];
    v.x *= inv; v.y *= inv; v.z *= inv; v.w *= inv;
    *(float4*)(p + tid * 4) = v;
}

// ---------------------------------------------------------------------------
// Context: per (b,h): CTX = attn @ V[1024,64]. bf16-3x, k16 MMA.
// BM=128, BN=64. grid = (1, 8, 128).
// ---------------------------------------------------------------------------
__global__ __launch_bounds__(256) void mma_av_kernel(
    const float* __restrict__ S, const float* __restrict__ Vg, float* __restrict__ CTX)
{
    const int z = blockIdx.z, b = z >> 4, h = z & 15;
    const float* A  = S + (size_t)z * LSEQ * LSEQ;
    const float* Bp = Vg + (size_t)b * LSEQ * DMODEL + h * DHEAD;
    float* C = CTX + (size_t)b * LSEQ * DMODEL + h * DHEAD;

    __shared__ unsigned AsH[8][PAD_A], AsL[8][PAD_A];
    __shared__ unsigned BsH[8][PAD_B], BsL[8][PAD_B];

    const int tid = threadIdx.x;
    const int wid = tid >> 5, lane = tid & 31;
    const int gid = lane >> 2, tig = lane & 3;
    const int wm = (wid & 1) * 64, wn = (wid >> 1) * 16;
    const int bm = blockIdx.y * 128;

    float acc[4][2][4] = {};

    for (int k0 = 0; k0 < LSEQ; k0 += 16) {
        #pragma unroll
        for (int t = 0; t < 2; t++) {
            int id = tid + t * 256;
            int r = id >> 2, c = (id & 3) << 2, k2 = c >> 1;
            float4 v = *(const float4*)(A + (size_t)(bm + r) * LSEQ + k0 + c);
            unsigned h0, l0, h1, l1;
            bf16_split2(v.x, v.y, h0, l0);
            bf16_split2(v.z, v.w, h1, l1);
            AsH[k2][r] = h0; AsL[k2][r] = l0;
            AsH[k2 + 1][r] = h1; AsL[k2 + 1][r] = l1;
        }
        if (tid < 128) {
            int k2 = tid >> 4, n = (tid & 15) << 2;
            const float* p = Bp + (size_t)(k0 + 2 * k2) * DMODEL + n;
            float4 r0 = *(const float4*)p;
            float4 r1 = *(const float4*)(p + DMODEL);
            unsigned h, l;
            bf16_split2(r0.x, r1.x, h, l); BsH[k2][n]     = h; BsL[k2][n]     = l;
            bf16_split2(r0.y, r1.y, h, l); BsH[k2][n + 1] = h; BsL[k2][n + 1] = l;
            bf16_split2(r0.z, r1.z, h, l); BsH[k2][n + 2] = h; BsL[k2][n + 2] = l;
            bf16_split2(r0.w, r1.w, h, l); BsH[k2][n + 3] = h; BsL[k2][n + 3] = l;
        }
        __syncthreads();

        unsigned aH[4][4], aL[4][4];
        #pragma unroll
        for (int mf = 0; mf < 4; mf++) {
            frag_a(AsH, tig, wm + mf * 16 + gid, aH[mf]);
            frag_a(AsL, tig, wm + mf * 16 + gid, aL[mf]);
        }
        #pragma unroll
        for (int nf = 0; nf < 2; nf++) {
            int n = wn + nf * 8 + gid;
            unsigned bH[2] = { BsH[tig][n], BsH[tig + 4][n] };
            unsigned bL[2] = { BsL[tig][n], BsL[tig + 4][n] };
            #pragma unroll
            for (int mf = 0; mf < 4; mf++) {
                mma16(acc[mf][nf], aH[mf], bH);
                mma16(acc[mf][nf], aH[mf], bL);
                mma16(acc[mf][nf], aL[mf], bH);
            }
        }
        __syncthreads();
    }

    #pragma unroll
    for (int mf = 0; mf < 4; mf++) {
        #pragma unroll
        for (int nf = 0; nf < 2; nf++) {
            int m = bm + wm + mf * 16 + gid;
            int n = wn + nf * 8 + 2 * tig;
            *(float2*)(C + (size_t)m * DMODEL + n) =
                make_float2(acc[mf][nf][0], acc[mf][nf][1]);
            *(float2*)(C + (size_t)(m + 8) * DMODEL + n) =
                make_float2(acc[mf][nf][2], acc[mf][nf][3]);
        }
    }
}

// ---------------------------------------------------------------------------
__global__ __launch_bounds__(256) void ln_kernel(
    const float* __restrict__ Y, float* __restrict__ O,
    const float* __restrict__ gamma, const float* __restrict__ beta)
{
    __shared__ float red[256];
    const float* p = Y + (size_t)blockIdx.x * DMODEL;
    const int tid = threadIdx.x;
    float4 v = *(const float4*)(p + tid * 4);
    red[tid] = v.x + v.y + v.z + v.w;
    __syncthreads();
    for (int s = 128; s > 0; s >>= 1) {
        if (tid < s) red[tid] += red[tid + s];
        __syncthreads();
    }
    const float mu = red[0] * (1.0f / DMODEL);
    __syncthreads();
    const float dx = v.x - mu, dy = v.y - mu, dz = v.z - mu, dw = v.w - mu;
    red[tid] = dx * dx + dy * dy + dz * dz + dw * dw;
    __syncthreads();
    for (int s = 128; s > 0; s >>= 1) {
        if (tid < s) red[tid] += red[tid + s];
        __syncthreads();
    }
    const float rstd = rsqrtf(red[0] * (1.0f / DMODEL) + 1e-6f);
    const float4 g  = *(const float4*)(gamma + tid * 4);
    const float4 be = *(const float4*)(beta + tid * 4);
    float4 o;
    o.x = dx * rstd * g.x + be.x;
    o.y = dy * rstd * g.y + be.y;
    o.z = dz * rstd * g.z + be.z;
    o.w = dw * rstd * g.w + be.w;
    *(float4*)(O + (size_t)blockIdx.x * DMODEL + tid * 4) = o;
}

// ---------------------------------------------------------------------------
extern "C" void kernel_launch(void* const* d_in, const int* in_sizes, int n_in,
                              void* d_out, int out_size)
{
    const float* X    = (const float*)d_in[0];
    const unsigned int* mask = (const unsigned int*)d_in[1];
    const float* W_Q  = (const float*)d_in[2];
    const float* W_K  = (const float*)d_in[3];
    const float* W_V  = (const float*)d_in[4];
    const float* W_O  = (const float*)d_in[5];
    const float* gamma = (const float*)d_in[6];
    const float* beta  = (const float*)d_in[7];

    float *Qp, *Kp, *Vp, *Cp, *Yp, *Sp;
    cudaGetSymbolAddress((void**)&Qp, g_Q);
    cudaGetSymbolAddress((void**)&Kp, g_K);
    cudaGetSymbolAddress((void**)&Vp, g_V);
    cudaGetSymbolAddress((void**)&Cp, g_CTX);
    cudaGetSymbolAddress((void**)&Yp, g_Y);
    cudaGetSymbolAddress((void**)&Sp, g_S);

    const size_t LN_ELEMS   = (size_t)NROWS * DMODEL;
    const size_t ATTN_ELEMS = (size_t)NBATCH * NHEADS * LSEQ * LSEQ;

    float* out_ln;
    float* attn_dst;
    if ((size_t)out_size >= LN_ELEMS + ATTN_ELEMS) {
        out_ln = (float*)d_out;
        attn_dst = (float*)d_out + LN_ELEMS;
    } else if ((size_t)out_size == ATTN_ELEMS) {
        attn_dst = (float*)d_out;
        out_ln = Yp;
    } else {
        out_ln = (float*)d_out;
        attn_dst = Sp;
    }

    dim3 thr(256);
    mma_nn_kernel<<<dim3(8, 64), thr>>>(X, W_Q, Qp, nullptr, DMODEL);
    mma_nn_kernel<<<dim3(8, 64), thr>>>(X, W_K, Kp, nullptr, DMODEL);
    mma_nn_kernel<<<dim3(8, 64), thr>>>(X, W_V, Vp, nullptr, DMODEL);
    mma_scores_kernel<<<dim3(8, 8, NBATCH * NHEADS), thr>>>(Qp, Kp, attn_dst, mask);
    softmax_kernel<<<dim3(NBATCH * NHEADS * LSEQ), thr>>>(attn_dst);
    mma_av_kernel<<<dim3(1, 8, NBATCH * NHEADS), thr>>>(attn_dst, Vp, Cp);
    mma_nn_kernel<<<dim3(8, 64), thr>>>(Cp, W_O, Yp, X, DMODEL);
    ln_kernel<<<dim3(NROWS), thr>>>(Yp, out_ln, gamma, beta);
}

// round 9
// speedup vs baseline: 2.2336x; 1.0267x over previous
#include <cuda_runtime.h>
#include <cuda_bf16.h>
#include <math.h>

#define LSEQ   1024
#define DMODEL 1024
#define NHEADS 16
#define DHEAD  64
#define NBATCH 8
#define NROWS  (NBATCH * LSEQ)   // 8192

static __device__ float g_Q[NROWS * DMODEL];
static __device__ float g_K[NROWS * DMODEL];
static __device__ float g_V[NROWS * DMODEL];
static __device__ float g_CTX[NROWS * DMODEL];
static __device__ float g_Y[NROWS * DMODEL];
static __device__ float g_S[(size_t)NBATCH * NHEADS * LSEQ * LSEQ];

// ---------------------------------------------------------------------------
// Split two fp32 values (consecutive along k: x0 = even k, x1 = odd k) into
// packed bf16x2 hi and lo (residual) words.  lo half of word = x0.
// ---------------------------------------------------------------------------
__device__ __forceinline__ void bf16_split2(float x0, float x1,
                                            unsigned& hi_w, unsigned& lo_w) {
    asm("cvt.rn.bf16x2.f32 %0, %1, %2;" : "=r"(hi_w) : "f"(x1), "f"(x0));
    __nv_bfloat162 hv = *reinterpret_cast<__nv_bfloat162*>(&hi_w);
    float r0 = x0 - __bfloat162float(hv.x);
    float r1 = x1 - __bfloat162float(hv.y);
    asm("cvt.rn.bf16x2.f32 %0, %1, %2;" : "=r"(lo_w) : "f"(r1), "f"(r0));
}

// m16n8k16 bf16 MMA, fp32 accumulate
__device__ __forceinline__ void mma16(float* c, const unsigned* a, const unsigned* b) {
    asm volatile(
        "mma.sync.aligned.m16n8k16.row.col.f32.bf16.bf16.f32 "
        "{%0,%1,%2,%3}, {%4,%5,%6,%7}, {%8,%9}, {%0,%1,%2,%3};"
        : "+f"(c[0]), "+f"(c[1]), "+f"(c[2]), "+f"(c[3])
        : "r"(a[0]), "r"(a[1]), "r"(a[2]), "r"(a[3]), "r"(b[0]), "r"(b[1]));
}

#define PAD_A 136   // word stride: 136 mod 32 = 8 -> frag loads (8*tig+gid) conflict-free
#define PAD_B 72

// A-fragment load from packed transposed tile [k2][m]
__device__ __forceinline__ void frag_a(const unsigned (*T)[PAD_A], int tig, int m,
                                       unsigned* a) {
    a[0] = T[tig    ][m    ];
    a[1] = T[tig    ][m + 8];
    a[2] = T[tig + 4][m    ];
    a[3] = T[tig + 4][m + 8];
}

// ---------------------------------------------------------------------------
// Dense NN GEMM: C[M,1024] = A[M,K] @ B[K,1024] (+R). bf16-3x, k16 MMA.
// BM=BN=128, BK=16, 8 warps, warp tile 64x32. grid=(8, M/128).
// ---------------------------------------------------------------------------
__global__ __launch_bounds__(256, 2) void mma_nn_kernel(
    const float* __restrict__ A, const float* __restrict__ B,
    float* __restrict__ C, const float* __restrict__ R, int K)
{
    const int N = DMODEL;
    __shared__ unsigned AsH[8][PAD_A], AsL[8][PAD_A];   // transposed A, packed k-pairs
    __shared__ unsigned BsH[8][PAD_A], BsL[8][PAD_A];   // B, packed k-pairs

    const int tid = threadIdx.x;
    const int wid = tid >> 5, lane = tid & 31;
    const int gid = lane >> 2, tig = lane & 3;
    const int wm = (wid & 1) * 64, wn = (wid >> 1) * 32;
    const int bm = blockIdx.y * 128, bn = blockIdx.x * 128;

    float acc[4][4][4] = {};

    for (int k0 = 0; k0 < K; k0 += 16) {
        // A tile 128x16 -> transposed packed [k2][m]
        #pragma unroll
        for (int t = 0; t < 2; t++) {
            int id = tid + t * 256;
            int r = id >> 2, c = (id & 3) << 2, k2 = c >> 1;
            float4 v = *(const float4*)(A + (size_t)(bm + r) * K + k0 + c);
            unsigned h0, l0, h1, l1;
            bf16_split2(v.x, v.y, h0, l0);
            bf16_split2(v.z, v.w, h1, l1);
            AsH[k2][r] = h0; AsL[k2][r] = l0;
            AsH[k2 + 1][r] = h1; AsL[k2 + 1][r] = l1;
        }
        // B tile 16x128 -> packed [k2][n]; pair two consecutive k rows
        {
            int k2 = tid >> 5, n = (tid & 31) << 2;
            const float* p = B + (size_t)(k0 + 2 * k2) * N + bn + n;
            float4 r0 = *(const float4*)p;
            float4 r1 = *(const float4*)(p + N);
            unsigned h, l;
            bf16_split2(r0.x, r1.x, h, l); BsH[k2][n]     = h; BsL[k2][n]     = l;
            bf16_split2(r0.y, r1.y, h, l); BsH[k2][n + 1] = h; BsL[k2][n + 1] = l;
            bf16_split2(r0.z, r1.z, h, l); BsH[k2][n + 2] = h; BsL[k2][n + 2] = l;
            bf16_split2(r0.w, r1.w, h, l); BsH[k2][n + 3] = h; BsL[k2][n + 3] = l;
        }
        __syncthreads();

        unsigned aH[4][4], aL[4][4];
        #pragma unroll
        for (int mf = 0; mf < 4; mf++) {
            frag_a(AsH, tig, wm + mf * 16 + gid, aH[mf]);
            frag_a(AsL, tig, wm + mf * 16 + gid, aL[mf]);
        }
        #pragma unroll
        for (int nf = 0; nf < 4; nf++) {
            int n = wn + nf * 8 + gid;
            unsigned bH[2] = { BsH[tig][n], BsH[tig + 4][n] };
            unsigned bL[2] = { BsL[tig][n], BsL[tig + 4][n] };
            #pragma unroll
            for (int mf = 0; mf < 4; mf++) {
                mma16(acc[mf][nf], aH[mf], bH);
                mma16(acc[mf][nf], aH[mf], bL);
                mma16(acc[mf][nf], aL[mf], bH);
            }
        }
        __syncthreads();
    }

    #pragma unroll
    for (int mf = 0; mf < 4; mf++) {
        #pragma unroll
        for (int nf = 0; nf < 4; nf++) {
            int m = bm + wm + mf * 16 + gid;
            int n = bn + wn + nf * 8 + 2 * tig;
            float2 v0 = make_float2(acc[mf][nf][0], acc[mf][nf][1]);
            float2 v1 = make_float2(acc[mf][nf][2], acc[mf][nf][3]);
            if (R) {
                float2 r0 = *(const float2*)(R + (size_t)m * N + n);
                float2 r1 = *(const float2*)(R + (size_t)(m + 8) * N + n);
                v0.x += r0.x; v0.y += r0.y; v1.x += r1.x; v1.y += r1.y;
            }
            *(float2*)(C + (size_t)m * N + n) = v0;
            *(float2*)(C + (size_t)(m + 8) * N + n) = v1;
        }
    }
}

// ---------------------------------------------------------------------------
// Scores: per (b,h): S = 0.125 * Q @ K^T, masked. bf16-3x, k16 MMA.
// grid = (8, 8, 128).
// ---------------------------------------------------------------------------
__global__ __launch_bounds__(256, 2) void mma_scores_kernel(
    const float* __restrict__ Qg, const float* __restrict__ Kg,
    float* __restrict__ S, const unsigned int* __restrict__ mask)
{
    const int z = blockIdx.z, b = z >> 4, h = z & 15;
    const float* Aq = Qg + (size_t)b * LSEQ * DMODEL + h * DHEAD;
    const float* Bk = Kg + (size_t)b * LSEQ * DMODEL + h * DHEAD;
    float* C = S + (size_t)z * LSEQ * LSEQ;
    const unsigned int* mb = mask + (size_t)b * LSEQ * LSEQ;

    __shared__ unsigned AsH[8][PAD_A], AsL[8][PAD_A];
    __shared__ unsigned BsH[8][PAD_A], BsL[8][PAD_A];

    const int tid = threadIdx.x;
    const int wid = tid >> 5, lane = tid & 31;
    const int gid = lane >> 2, tig = lane & 3;
    const int wm = (wid & 1) * 64, wn = (wid >> 1) * 32;
    const int bm = blockIdx.y * 128, bn = blockIdx.x * 128;

    float acc[4][4][4] = {};

    for (int k0 = 0; k0 < DHEAD; k0 += 16) {
        #pragma unroll
        for (int t = 0; t < 2; t++) {
            int id = tid + t * 256;
            int r = id >> 2, c = (id & 3) << 2, k2 = c >> 1;
            float4 v = *(const float4*)(Aq + (size_t)(bm + r) * DMODEL + k0 + c);
            unsigned h0, l0, h1, l1;
            bf16_split2(v.x, v.y, h0, l0);
            bf16_split2(v.z, v.w, h1, l1);
            AsH[k2][r] = h0; AsL[k2][r] = l0;
            AsH[k2 + 1][r] = h1; AsL[k2 + 1][r] = l1;
            float4 w = *(const float4*)(Bk + (size_t)(bn + r) * DMODEL + k0 + c);
            bf16_split2(w.x, w.y, h0, l0);
            bf16_split2(w.z, w.w, h1, l1);
            BsH[k2][r] = h0; BsL[k2][r] = l0;
            BsH[k2 + 1][r] = h1; BsL[k2 + 1][r] = l1;
        }
        __syncthreads();

        unsigned aH[4][4], aL[4][4];
        #pragma unroll
        for (int mf = 0; mf < 4; mf++) {
            frag_a(AsH, tig, wm + mf * 16 + gid, aH[mf]);
            frag_a(AsL, tig, wm + mf * 16 + gid, aL[mf]);
        }
        #pragma unroll
        for (int nf = 0; nf < 4; nf++) {
            int n = wn + nf * 8 + gid;
            unsigned bH[2] = { BsH[tig][n], BsH[tig + 4][n] };
            unsigned bL[2] = { BsL[tig][n], BsL[tig + 4][n] };
            #pragma unroll
            for (int mf = 0; mf < 4; mf++) {
                mma16(acc[mf][nf], aH[mf], bH);
                mma16(acc[mf][nf], aH[mf], bL);
                mma16(acc[mf][nf], aL[mf], bH);
            }
        }
        __syncthreads();
    }

    const float scale = 0.125f;
    #pragma unroll
    for (int mf = 0; mf < 4; mf++) {
        #pragma unroll
        for (int nf = 0; nf < 4; nf++) {
            int m = bm + wm + mf * 16 + gid;
            int n = bn + wn + nf * 8 + 2 * tig;
            #pragma unroll
            for (int half = 0; half < 2; half++) {
                int q = m + half * 8;
                float s0 = acc[mf][nf][half * 2]     * scale;
                float s1 = acc[mf][nf][half * 2 + 1] * scale;
                if (mb[(size_t)q * LSEQ + n]     != 0u) s0 = -1e9f;
                if (mb[(size_t)q * LSEQ + n + 1] != 0u) s1 = -1e9f;
                *(float2*)(C + (size_t)q * LSEQ + n) = make_float2(s0, s1);
            }
        }
    }
}

// ---------------------------------------------------------------------------
__global__ __launch_bounds__(256) void softmax_kernel(float* __restrict__ S)
{
    __shared__ float red[256];
    float* p = S + (size_t)blockIdx.x * LSEQ;
    const int tid = threadIdx.x;
    float4 v = *(float4*)(p + tid * 4);
    red[tid] = fmaxf(fmaxf(v.x, v.y), fmaxf(v.z, v.w));
    __syncthreads();
    for (int s = 128; s > 0; s >>= 1) {
        if (tid < s) red[tid] = fmaxf(red[tid], red[tid + s]);
        __syncthreads();
    }
    const float mx = red[0];
    __syncthreads();
    v.x = __expf(v.x - mx); v.y = __expf(v.y - mx);
    v.z = __expf(v.z - mx); v.w = __expf(v.w - mx);
    red[tid] = v.x + v.y + v.z + v.w;
    __syncthreads();
    for (int s = 128; s > 0; s >>= 1) {
        if (tid < s) red[tid] += red[tid + s];
        __syncthreads();
    }
    const float inv = 1.0f / red[0];
    v.x *= inv; v.y *= inv; v.z *= inv; v.w *= inv;
    *(float4*)(p + tid * 4) = v;
}

// ---------------------------------------------------------------------------
// Context: per (b,h): CTX = attn @ V[1024,64]. bf16-3x, k16 MMA.
// BM=128, BN=64. grid = (1, 8, 128).
// ---------------------------------------------------------------------------
__global__ __launch_bounds__(256, 2) void mma_av_kernel(
    const float* __restrict__ S, const float* __restrict__ Vg, float* __restrict__ CTX)
{
    const int z = blockIdx.z, b = z >> 4, h = z & 15;
    const float* A  = S + (size_t)z * LSEQ * LSEQ;
    const float* Bp = Vg + (size_t)b * LSEQ * DMODEL + h * DHEAD;
    float* C = CTX + (size_t)b * LSEQ * DMODEL + h * DHEAD;

    __shared__ unsigned AsH[8][PAD_A], AsL[8][PAD_A];
    __shared__ unsigned BsH[8][PAD_B], BsL[8][PAD_B];

    const int tid = threadIdx.x;
    const int wid = tid >> 5, lane = tid & 31;
    const int gid = lane >> 2, tig = lane & 3;
    const int wm = (wid & 1) * 64, wn = (wid >> 1) * 16;
    const int bm = blockIdx.y * 128;

    float acc[4][2][4] = {};

    for (int k0 = 0; k0 < LSEQ; k0 += 16) {
        #pragma unroll
        for (int t = 0; t < 2; t++) {
            int id = tid + t * 256;
            int r = id >> 2, c = (id & 3) << 2, k2 = c >> 1;
            float4 v = *(const float4*)(A + (size_t)(bm + r) * LSEQ + k0 + c);
            unsigned h0, l0, h1, l1;
            bf16_split2(v.x, v.y, h0, l0);
            bf16_split2(v.z, v.w, h1, l1);
            AsH[k2][r] = h0; AsL[k2][r] = l0;
            AsH[k2 + 1][r] = h1; AsL[k2 + 1][r] = l1;
        }
        if (tid < 128) {
            int k2 = tid >> 4, n = (tid & 15) << 2;
            const float* p = Bp + (size_t)(k0 + 2 * k2) * DMODEL + n;
            float4 r0 = *(const float4*)p;
            float4 r1 = *(const float4*)(p + DMODEL);
            unsigned h, l;
            bf16_split2(r0.x, r1.x, h, l); BsH[k2][n]     = h; BsL[k2][n]     = l;
            bf16_split2(r0.y, r1.y, h, l); BsH[k2][n + 1] = h; BsL[k2][n + 1] = l;
            bf16_split2(r0.z, r1.z, h, l); BsH[k2][n + 2] = h; BsL[k2][n + 2] = l;
            bf16_split2(r0.w, r1.w, h, l); BsH[k2][n + 3] = h; BsL[k2][n + 3] = l;
        }
        __syncthreads();

        unsigned aH[4][4], aL[4][4];
        #pragma unroll
        for (int mf = 0; mf < 4; mf++) {
            frag_a(AsH, tig, wm + mf * 16 + gid, aH[mf]);
            frag_a(AsL, tig, wm + mf * 16 + gid, aL[mf]);
        }
        #pragma unroll
        for (int nf = 0; nf < 2; nf++) {
            int n = wn + nf * 8 + gid;
            unsigned bH[2] = { BsH[tig][n], BsH[tig + 4][n] };
            unsigned bL[2] = { BsL[tig][n], BsL[tig + 4][n] };
            #pragma unroll
            for (int mf = 0; mf < 4; mf++) {
                mma16(acc[mf][nf], aH[mf], bH);
                mma16(acc[mf][nf], aH[mf], bL);
                mma16(acc[mf][nf], aL[mf], bH);
            }
        }
        __syncthreads();
    }

    #pragma unroll
    for (int mf = 0; mf < 4; mf++) {
        #pragma unroll
        for (int nf = 0; nf < 2; nf++) {
            int m = bm + wm + mf * 16 + gid;
            int n = wn + nf * 8 + 2 * tig;
            *(float2*)(C + (size_t)m * DMODEL + n) =
                make_float2(acc[mf][nf][0], acc[mf][nf][1]);
            *(float2*)(C + (size_t)(m + 8) * DMODEL + n) =
                make_float2(acc[mf][nf][2], acc[mf][nf][3]);
        }
    }
}

// ---------------------------------------------------------------------------
__global__ __launch_bounds__(256) void ln_kernel(
    const float* __restrict__ Y, float* __restrict__ O,
    const float* __restrict__ gamma, const float* __restrict__ beta)
{
    __shared__ float red[256];
    const float* p = Y + (size_t)blockIdx.x * DMODEL;
    const int tid = threadIdx.x;
    float4 v = *(const float4*)(p + tid * 4);
    red[tid] = v.x + v.y + v.z + v.w;
    __syncthreads();
    for (int s = 128; s > 0; s >>= 1) {
        if (tid < s) red[tid] += red[tid + s];
        __syncthreads();
    }
    const float mu = red[0] * (1.0f / DMODEL);
    __syncthreads();
    const float dx = v.x - mu, dy = v.y - mu, dz = v.z - mu, dw = v.w - mu;
    red[tid] = dx * dx + dy * dy + dz * dz + dw * dw;
    __syncthreads();
    for (int s = 128; s > 0; s >>= 1) {
        if (tid < s) red[tid] += red[tid + s];
        __syncthreads();
    }
    const float rstd = rsqrtf(red[0] * (1.0f / DMODEL) + 1e-6f);
    const float4 g  = *(const float4*)(gamma + tid * 4);
    const float4 be = *(const float4*)(beta + tid * 4);
    float4 o;
    o.x = dx * rstd * g.x + be.x;
    o.y = dy * rstd * g.y + be.y;
    o.z = dz * rstd * g.z + be.z;
    o.w = dw * rstd * g.w + be.w;
    *(float4*)(O + (size_t)blockIdx.x * DMODEL + tid * 4) = o;
}

// ---------------------------------------------------------------------------
extern "C" void kernel_launch(void* const* d_in, const int* in_sizes, int n_in,
                              void* d_out, int out_size)
{
    const float* X    = (const float*)d_in[0];
    const unsigned int* mask = (const unsigned int*)d_in[1];
    const float* W_Q  = (const float*)d_in[2];
    const float* W_K  = (const float*)d_in[3];
    const float* W_V  = (const float*)d_in[4];
    const float* W_O  = (const float*)d_in[5];
    const float* gamma = (const float*)d_in[6];
    const float* beta  = (const float*)d_in[7];

    float *Qp, *Kp, *Vp, *Cp, *Yp, *Sp;
    cudaGetSymbolAddress((void**)&Qp, g_Q);
    cudaGetSymbolAddress((void**)&Kp, g_K);
    cudaGetSymbolAddress((void**)&Vp, g_V);
    cudaGetSymbolAddress((void**)&Cp, g_CTX);
    cudaGetSymbolAddress((void**)&Yp, g_Y);
    cudaGetSymbolAddress((void**)&Sp, g_S);

    const size_t LN_ELEMS   = (size_t)NROWS * DMODEL;
    const size_t ATTN_ELEMS = (size_t)NBATCH * NHEADS * LSEQ * LSEQ;

    float* out_ln;
    float* attn_dst;
    if ((size_t)out_size >= LN_ELEMS + ATTN_ELEMS) {
        out_ln = (float*)d_out;
        attn_dst = (float*)d_out + LN_ELEMS;
    } else if ((size_t)out_size == ATTN_ELEMS) {
        attn_dst = (float*)d_out;
        out_ln = Yp;
    } else {
        out_ln = (float*)d_out;
        attn_dst = Sp;
    }

    dim3 thr(256);
    mma_nn_kernel<<<dim3(8, 64), thr>>>(X, W_Q, Qp, nullptr, DMODEL);
    mma_nn_kernel<<<dim3(8, 64), thr>>>(X, W_K, Kp, nullptr, DMODEL);
    mma_nn_kernel<<<dim3(8, 64), thr>>>(X, W_V, Vp, nullptr, DMODEL);
    mma_scores_kernel<<<dim3(8, 8, NBATCH * NHEADS), thr>>>(Qp, Kp, attn_dst, mask);
    softmax_kernel<<<dim3(NBATCH * NHEADS * LSEQ), thr>>>(attn_dst);
    mma_av_kernel<<<dim3(1, 8, NBATCH * NHEADS), thr>>>(attn_dst, Vp, Cp);
    mma_nn_kernel<<<dim3(8, 64), thr>>>(Cp, W_O, Yp, X, DMODEL);
    ln_kernel<<<dim3(NROWS), thr>>>(Yp, out_ln, gamma, beta);
}